// round 1
// baseline (speedup 1.0000x reference)
#include <cuda_runtime.h>
#include <cuda_bf16.h>
#include <float.h>

#define N_NODES 100000
#define N_EDGES 1600000
#define ETOT    (N_EDGES + N_NODES)   // 1700000 (self-loops appended)
#define FDIM    32
#define NEG_SLOPE 0.2f

// ---------------- scratch (static device globals; no allocation) ------------
__device__ float g_xl [N_NODES * FDIM];   // source-transformed features
__device__ float g_xr [N_NODES * FDIM];   // target-transformed features
__device__ float g_h  [N_NODES * FDIM];   // layer-1 output (after relu)
__device__ float g_acc[N_NODES * FDIM];   // unnormalized aggregation
__device__ float g_s  [ETOT];             // per-edge raw scores
__device__ float g_m  [N_NODES];          // segment max
__device__ float g_z  [N_NODES];          // segment sum of exp
__device__ float g_cnt [N_NODES];         // in-degree (float, matches ref)
__device__ float g_suma[N_NODES];         // sum of edge_attr per target
__device__ float g_mean[N_NODES];         // self-loop attr (mean fill)

// order-preserving float atomic max (exact). init must be -FLT_MAX.
__device__ __forceinline__ void atomicMaxF(float* addr, float v) {
    if (v >= 0.0f) atomicMax((int*)addr, __float_as_int(v));
    else           atomicMin((unsigned int*)addr, __float_as_uint(v));
}

// ---------------- kernels ---------------------------------------------------

// init per-layer state: m=-inf, z=0, acc=0; (mode==0 also zeros degree stats)
__global__ void k_init(int mode) {
    int i = blockIdx.x * blockDim.x + threadIdx.x;
    if (i < N_NODES) {
        g_m[i] = -FLT_MAX;
        g_z[i] = 0.0f;
        if (mode == 0) { g_cnt[i] = 0.0f; g_suma[i] = 0.0f; }
    }
    if (i < N_NODES * FDIM) g_acc[i] = 0.0f;
}

__global__ void k_stats(const int* __restrict__ dst, const float* __restrict__ ea) {
    int e = blockIdx.x * blockDim.x + threadIdx.x;
    if (e < N_EDGES) {
        int d = dst[e];
        atomicAdd(&g_cnt[d], 1.0f);
        atomicAdd(&g_suma[d], ea[e]);
    }
}

__global__ void k_mean() {
    int i = blockIdx.x * blockDim.x + threadIdx.x;
    if (i < N_NODES) g_mean[i] = g_suma[i] / fmaxf(g_cnt[i], 1.0f);
}

// X[rows,K] @ Wl/Wr[K,32] + b -> g_xl/g_xr.  32 rows per block, 4 rows/thread.
template <int K>
__global__ void k_gemm(const float* __restrict__ Xin,
                       const float* __restrict__ Wl, const float* __restrict__ bl,
                       const float* __restrict__ Wr, const float* __restrict__ br) {
    __shared__ float sWl[K * 32];
    __shared__ float sWr[K * 32];
    __shared__ float sx [32 * K];
    const float* X = Xin ? Xin : g_h;
    int tid  = threadIdx.x;
    int base = blockIdx.x * 32;

    for (int i = tid; i < K * 32; i += 256) { sWl[i] = Wl[i]; sWr[i] = Wr[i]; }
    for (int i = tid; i < 32 * K; i += 256) { sx[i] = X[(long)base * K + i]; }
    __syncthreads();

    int col = tid & 31;
    int ty  = tid >> 5;            // 0..7 -> 4 rows each
    float al[4] = {0.f, 0.f, 0.f, 0.f};
    float ar[4] = {0.f, 0.f, 0.f, 0.f};

    #pragma unroll 8
    for (int k = 0; k < K; k++) {
        float wl = sWl[k * 32 + col];
        float wr = sWr[k * 32 + col];
        #pragma unroll
        for (int r = 0; r < 4; r++) {
            float xv = sx[(ty * 4 + r) * K + k];   // broadcast within warp
            al[r] = fmaf(xv, wl, al[r]);
            ar[r] = fmaf(xv, wr, ar[r]);
        }
    }
    #pragma unroll
    for (int r = 0; r < 4; r++) {
        int row = base + ty * 4 + r;
        g_xl[row * 32 + col] = al[r] + bl[col];
        g_xr[row * 32 + col] = ar[r] + br[col];
    }
}

// warp per edge: score + segment max
__global__ void k_scores(const int* __restrict__ src, const int* __restrict__ dst,
                         const float* __restrict__ ea,
                         const float* __restrict__ We, const float* __restrict__ att) {
    int g    = blockIdx.x * blockDim.x + threadIdx.x;
    int e    = g >> 5;
    int lane = g & 31;
    if (e >= ETOT) return;
    int s, d; float a;
    if (e < N_EDGES) { s = src[e]; d = dst[e]; a = ea[e]; }
    else             { s = e - N_EDGES; d = s; a = g_mean[s]; }

    float v = g_xl[s * 32 + lane] + g_xr[d * 32 + lane] + a * We[lane];
    v = v > 0.0f ? v : NEG_SLOPE * v;
    float t = v * att[lane];
    #pragma unroll
    for (int o = 16; o; o >>= 1) t += __shfl_xor_sync(0xffffffffu, t, o);
    if (lane == 0) {
        g_s[e] = t;
        atomicMaxF(&g_m[d], t);
    }
}

// warp per edge: p = exp(s-m[d]); acc[d] += p*xl[s]; z[d] += p  (normalize later)
__global__ void k_agg(const int* __restrict__ src, const int* __restrict__ dst) {
    int g    = blockIdx.x * blockDim.x + threadIdx.x;
    int e    = g >> 5;
    int lane = g & 31;
    if (e >= ETOT) return;
    int s, d;
    if (e < N_EDGES) { s = src[e]; d = dst[e]; }
    else             { s = e - N_EDGES; d = s; }

    float p = expf(g_s[e] - g_m[d]);
    atomicAdd(&g_acc[d * 32 + lane], p * g_xl[s * 32 + lane]);
    if (lane == 0) atomicAdd(&g_z[d], p);
}

// node-level finalize: divide by z, add bias; layer1 -> relu into g_h,
// layer2 -> write d_out.
__global__ void k_fin(const float* __restrict__ b, float* __restrict__ out, int do_relu) {
    int i = blockIdx.x * blockDim.x + threadIdx.x;
    if (i >= N_NODES * FDIM) return;
    float v = g_acc[i] / g_z[i >> 5] + b[i & 31];
    if (do_relu) g_h[i] = fmaxf(v, 0.0f);
    else         out[i] = v;
}

// ---------------- launch ----------------------------------------------------
extern "C" void kernel_launch(void* const* d_in, const int* in_sizes, int n_in,
                              void* d_out, int out_size) {
    const float* x    = (const float*)d_in[0];
    const int*   src  = (const int*)  d_in[1];
    const int*   dst  = (const int*)  d_in[2];
    const float* ea   = (const float*)d_in[3];
    const float* Wl1  = (const float*)d_in[4];
    const float* bl1  = (const float*)d_in[5];
    const float* Wr1  = (const float*)d_in[6];
    const float* br1  = (const float*)d_in[7];
    const float* We1  = (const float*)d_in[8];
    const float* att1 = (const float*)d_in[9];
    const float* b1   = (const float*)d_in[10];
    const float* Wl2  = (const float*)d_in[11];
    const float* bl2  = (const float*)d_in[12];
    const float* Wr2  = (const float*)d_in[13];
    const float* br2  = (const float*)d_in[14];
    const float* We2  = (const float*)d_in[15];
    const float* att2 = (const float*)d_in[16];
    const float* b2   = (const float*)d_in[17];
    float* out = (float*)d_out;

    const int TB  = 256;
    const int NB32 = (N_NODES * FDIM + TB - 1) / TB;   // covers N and N*32
    const int NB   = (N_NODES + TB - 1) / TB;
    const int EB   = (N_EDGES + TB - 1) / TB;
    const int SB   = (ETOT * 32 + TB - 1) / TB;        // warp per edge
    const int GB   = N_NODES / 32;                     // 3125, exact

    // self-loop mean attrs (layer-invariant) + layer-1 state
    k_init<<<NB32, TB>>>(0);
    k_stats<<<EB, TB>>>(dst, ea);
    k_mean<<<NB, TB>>>();

    // ---- layer 1 ----
    k_gemm<128><<<GB, TB>>>(x, Wl1, bl1, Wr1, br1);
    k_scores<<<SB, TB>>>(src, dst, ea, We1, att1);
    k_agg<<<SB, TB>>>(src, dst);
    k_fin<<<NB32, TB>>>(b1, out, 1);

    // ---- layer 2 ----
    k_init<<<NB32, TB>>>(1);
    k_gemm<32><<<GB, TB>>>(nullptr, Wl2, bl2, Wr2, br2);
    k_scores<<<SB, TB>>>(src, dst, ea, We2, att2);
    k_agg<<<SB, TB>>>(src, dst);
    k_fin<<<NB32, TB>>>(b2, out, 0);
}

// round 3
// speedup vs baseline: 2.8595x; 2.8595x over previous
#include <cuda_runtime.h>
#include <cuda_bf16.h>
#include <float.h>

#define N_NODES 100000
#define N_EDGES 1600000
#define ETOT    (N_EDGES + N_NODES)   // self-loops appended at [E, E+N)
#define FDIM    32
#define NEG_SLOPE 0.2f

// ---------------- scratch (static device globals; no allocation) ------------
__device__ __align__(16) float g_xl [N_NODES * FDIM];   // source transform
__device__ __align__(16) float g_xr [N_NODES * FDIM];   // target transform
__device__ __align__(16) float g_h  [N_NODES * FDIM];   // layer-1 output (relu'd)
__device__ __align__(16) float g_acc[N_NODES * FDIM];   // unnormalized aggregation
__device__ float g_z   [N_NODES];         // sum of exp(score) per target
__device__ float g_cnt [N_NODES];         // in-degree
__device__ float g_suma[N_NODES];         // sum of edge_attr per target
__device__ float g_mean[N_NODES];         // self-loop attr (mean fill)

// ---------------- kernels ---------------------------------------------------

// init per-layer state: z=0, acc=0; (mode==0 also zeros degree stats)
__global__ void k_init(int mode) {
    int i = blockIdx.x * blockDim.x + threadIdx.x;
    if (i < N_NODES) {
        g_z[i] = 0.0f;
        if (mode == 0) { g_cnt[i] = 0.0f; g_suma[i] = 0.0f; }
    }
    if (i < N_NODES * FDIM) g_acc[i] = 0.0f;
}

__global__ void k_stats(const int* __restrict__ dst, const float* __restrict__ ea) {
    int e = blockIdx.x * blockDim.x + threadIdx.x;
    if (e < N_EDGES) {
        int d = dst[e];
        atomicAdd(&g_cnt[d], 1.0f);
        atomicAdd(&g_suma[d], ea[e]);
    }
}

__global__ void k_mean() {
    int i = blockIdx.x * blockDim.x + threadIdx.x;
    if (i < N_NODES) g_mean[i] = g_suma[i] / fmaxf(g_cnt[i], 1.0f);
}

// X[rows,K] @ Wl/Wr[K,32] + bias -> g_xl/g_xr.
// 64 rows/block, 256 threads: warp w handles rows base+8w..+7, lane = out col.
// x read via LDG.128 broadcast (whole warp same address), W staged in SMEM.
template <int K>
__global__ void __launch_bounds__(256) k_gemm(
        const float4* __restrict__ Xin,
        const float* __restrict__ Wl, const float* __restrict__ bl,
        const float* __restrict__ Wr, const float* __restrict__ br) {
    __shared__ float sWl[K * 32];
    __shared__ float sWr[K * 32];
    const float4* X4 = Xin ? Xin : (const float4*)g_h;

    int tid = threadIdx.x;
    for (int i = tid; i < K * 32; i += 256) { sWl[i] = Wl[i]; sWr[i] = Wr[i]; }
    __syncthreads();

    int col  = tid & 31;
    int ty   = tid >> 5;
    int row0 = blockIdx.x * 64 + ty * 8;

    float al[8], ar[8];
    #pragma unroll
    for (int r = 0; r < 8; r++) { al[r] = 0.f; ar[r] = 0.f; }

    #pragma unroll 4
    for (int k4 = 0; k4 < K / 4; k4++) {
        float4 xv[8];
        #pragma unroll
        for (int r = 0; r < 8; r++) {
            int row = row0 + r;
            if (row >= N_NODES) row = N_NODES - 1;     // clamp (stores guarded)
            xv[r] = __ldg(&X4[(long)row * (K / 4) + k4]);
        }
        float wl0 = sWl[(k4 * 4 + 0) * 32 + col];
        float wl1 = sWl[(k4 * 4 + 1) * 32 + col];
        float wl2 = sWl[(k4 * 4 + 2) * 32 + col];
        float wl3 = sWl[(k4 * 4 + 3) * 32 + col];
        float wr0 = sWr[(k4 * 4 + 0) * 32 + col];
        float wr1 = sWr[(k4 * 4 + 1) * 32 + col];
        float wr2 = sWr[(k4 * 4 + 2) * 32 + col];
        float wr3 = sWr[(k4 * 4 + 3) * 32 + col];
        #pragma unroll
        for (int r = 0; r < 8; r++) {
            al[r] = fmaf(xv[r].x, wl0, al[r]);
            al[r] = fmaf(xv[r].y, wl1, al[r]);
            al[r] = fmaf(xv[r].z, wl2, al[r]);
            al[r] = fmaf(xv[r].w, wl3, al[r]);
            ar[r] = fmaf(xv[r].x, wr0, ar[r]);
            ar[r] = fmaf(xv[r].y, wr1, ar[r]);
            ar[r] = fmaf(xv[r].z, wr2, ar[r]);
            ar[r] = fmaf(xv[r].w, wr3, ar[r]);
        }
    }
    float bL = bl[col], bR = br[col];
    #pragma unroll
    for (int r = 0; r < 8; r++) {
        int row = row0 + r;
        if (row < N_NODES) {
            g_xl[row * 32 + col] = al[r] + bL;
            g_xr[row * 32 + col] = ar[r] + bR;
        }
    }
}

// Fused edge pass: 8 lanes per edge, each lane owns a float4 feature group.
// score -> p = exp(score) (shift-invariant softmax, no max pass) ->
// acc[d] += p * xl[s]  (red.v4),  z[d] += p.
__global__ void k_edge(const int* __restrict__ src, const int* __restrict__ dst,
                       const float* __restrict__ ea,
                       const float* __restrict__ We, const float* __restrict__ att) {
    int g   = blockIdx.x * blockDim.x + threadIdx.x;
    int e   = g >> 3;
    int sub = g & 7;
    if (e >= ETOT) return;

    int s, d; float a;
    if (e < N_EDGES) { s = src[e]; d = dst[e]; a = ea[e]; }
    else             { s = e - N_EDGES; d = s; a = g_mean[s]; }

    // issue long-latency gathers first
    float4 xl4 = __ldg(&((const float4*)g_xl)[s * 8 + sub]);
    float4 xr4 = __ldg(&((const float4*)g_xr)[d * 8 + sub]);
    float4 W4  = __ldg(&((const float4*)We)[sub]);
    float4 A4  = __ldg(&((const float4*)att)[sub]);

    float v0 = xl4.x + xr4.x + a * W4.x;
    float v1 = xl4.y + xr4.y + a * W4.y;
    float v2 = xl4.z + xr4.z + a * W4.z;
    float v3 = xl4.w + xr4.w + a * W4.w;
    v0 = v0 > 0.f ? v0 : NEG_SLOPE * v0;
    v1 = v1 > 0.f ? v1 : NEG_SLOPE * v1;
    v2 = v2 > 0.f ? v2 : NEG_SLOPE * v2;
    v3 = v3 > 0.f ? v3 : NEG_SLOPE * v3;

    float t = v0 * A4.x + v1 * A4.y + v2 * A4.z + v3 * A4.w;
    t += __shfl_xor_sync(0xffffffffu, t, 1);
    t += __shfl_xor_sync(0xffffffffu, t, 2);
    t += __shfl_xor_sync(0xffffffffu, t, 4);

    float p = __expf(t);

    float c0 = p * xl4.x, c1 = p * xl4.y, c2 = p * xl4.z, c3 = p * xl4.w;
    float* dstp = &g_acc[d * 32 + sub * 4];
    asm volatile("red.global.add.v4.f32 [%0], {%1, %2, %3, %4};"
                 :: "l"(dstp), "f"(c0), "f"(c1), "f"(c2), "f"(c3) : "memory");
    if (sub == 0) atomicAdd(&g_z[d], p);
}

// finalize: divide by z, add bias; layer1 -> relu into g_h, layer2 -> d_out
__global__ void k_fin(const float* __restrict__ b, float* __restrict__ out, int do_relu) {
    int i = blockIdx.x * blockDim.x + threadIdx.x;
    if (i >= N_NODES * FDIM) return;
    float v = g_acc[i] / g_z[i >> 5] + b[i & 31];
    if (do_relu) g_h[i] = fmaxf(v, 0.0f);
    else         out[i] = v;
}

// ---------------- launch ----------------------------------------------------
extern "C" void kernel_launch(void* const* d_in, const int* in_sizes, int n_in,
                              void* d_out, int out_size) {
    const float* x    = (const float*)d_in[0];
    const int*   src  = (const int*)  d_in[1];
    const int*   dst  = (const int*)  d_in[2];
    const float* ea   = (const float*)d_in[3];
    const float* Wl1  = (const float*)d_in[4];
    const float* bl1  = (const float*)d_in[5];
    const float* Wr1  = (const float*)d_in[6];
    const float* br1  = (const float*)d_in[7];
    const float* We1  = (const float*)d_in[8];
    const float* att1 = (const float*)d_in[9];
    const float* b1   = (const float*)d_in[10];
    const float* Wl2  = (const float*)d_in[11];
    const float* bl2  = (const float*)d_in[12];
    const float* Wr2  = (const float*)d_in[13];
    const float* br2  = (const float*)d_in[14];
    const float* We2  = (const float*)d_in[15];
    const float* att2 = (const float*)d_in[16];
    const float* b2   = (const float*)d_in[17];
    float* out = (float*)d_out;

    const int TB   = 256;
    const int NB32 = (N_NODES * FDIM + TB - 1) / TB;
    const int NB   = (N_NODES + TB - 1) / TB;
    const int EB   = (N_EDGES + TB - 1) / TB;
    const int XB   = ((long)ETOT * 8 + TB - 1) / TB;   // oct per edge
    const int GB   = (N_NODES + 63) / 64;

    // self-loop mean attrs (layer-invariant) + layer-1 state
    k_init<<<NB32, TB>>>(0);
    k_stats<<<EB, TB>>>(dst, ea);
    k_mean<<<NB, TB>>>();

    // ---- layer 1 ----
    k_gemm<128><<<GB, TB>>>((const float4*)x, Wl1, bl1, Wr1, br1);
    k_edge<<<XB, TB>>>(src, dst, ea, We1, att1);
    k_fin<<<NB32, TB>>>(b1, out, 1);

    // ---- layer 2 ----
    k_init<<<NB32, TB>>>(1);
    k_gemm<32><<<GB, TB>>>(nullptr, Wl2, bl2, Wr2, br2);
    k_edge<<<XB, TB>>>(src, dst, ea, We2, att2);
    k_fin<<<NB32, TB>>>(b2, out, 0);
}

// round 7
// speedup vs baseline: 3.2643x; 1.1416x over previous
#include <cuda_runtime.h>
#include <cuda_bf16.h>
#include <float.h>

#define N_NODES 100000
#define N_EDGES 1600000
#define ETOT    (N_EDGES + N_NODES)   // self-loops appended at [E, E+N)
#define FDIM    32
#define NEG_SLOPE 0.2f

// ---------------- scratch (static device globals; no allocation) ------------
__device__ __align__(16) float g_xl [N_NODES * FDIM];   // source transform
__device__ __align__(16) float g_xr [N_NODES * FDIM];   // target transform
__device__ __align__(16) float g_h  [N_NODES * FDIM];   // layer-1 output (relu'd)
__device__ __align__(16) float g_acc[N_NODES * FDIM];   // unnormalized aggregation
__device__ float g_z1  [N_NODES];         // sum of exp(score), layer 1
__device__ float g_z2  [N_NODES];         // sum of exp(score), layer 2
__device__ float g_cnt [N_NODES];         // in-degree
__device__ float g_suma[N_NODES];         // sum of edge_attr per target
__device__ float g_mean[N_NODES];         // self-loop attr (mean fill)

// ---------------- kernels ---------------------------------------------------

// init (runs once per launch): z1=z2=0, acc=0, degree stats=0
__global__ void k_init() {
    int i = blockIdx.x * blockDim.x + threadIdx.x;
    if (i < N_NODES) { g_z1[i] = 0.0f; g_z2[i] = 0.0f; g_cnt[i] = 0.0f; g_suma[i] = 0.0f; }
    if (i < N_NODES * FDIM) g_acc[i] = 0.0f;
}

__global__ void k_stats(const int* __restrict__ dst, const float* __restrict__ ea) {
    int e = blockIdx.x * blockDim.x + threadIdx.x;
    if (e < N_EDGES) {
        int d = dst[e];
        atomicAdd(&g_cnt[d], 1.0f);
        atomicAdd(&g_suma[d], ea[e]);
    }
}

__global__ void k_mean() {
    int i = blockIdx.x * blockDim.x + threadIdx.x;
    if (i < N_NODES) g_mean[i] = g_suma[i] / fmaxf(g_cnt[i], 1.0f);
}

// X[rows,K] @ Wl/Wr[K,32] + bias -> g_xl/g_xr.
// 64 rows/block, 256 threads; warp w = rows base+8w..+7, lane = out col.
// x staged in SMEM (32KB max, coalesced fill), inner reads are warp-uniform
// broadcast LDS.128. W (16KB each, L1-resident) read via coalesced __ldg.
template <int K>
__global__ void __launch_bounds__(256) k_gemm(
        const float4* __restrict__ Xin,
        const float* __restrict__ Wl, const float* __restrict__ bl,
        const float* __restrict__ Wr, const float* __restrict__ br) {
    __shared__ float4 sx[64 * (K / 4)];              // 32KB (K=128) / 8KB (K=32)
    const float4* X4 = Xin ? Xin : (const float4*)g_h;

    int tid  = threadIdx.x;
    int base = blockIdx.x * 64;
    for (int i = tid; i < 64 * (K / 4); i += 256) {
        int row = base + i / (K / 4);
        int kk  = i % (K / 4);
        if (row >= N_NODES) row = N_NODES - 1;       // clamp (stores guarded)
        sx[i] = X4[(long)row * (K / 4) + kk];
    }
    __syncthreads();

    int col = tid & 31;
    int ty  = tid >> 5;

    float al[8], ar[8];
    #pragma unroll
    for (int r = 0; r < 8; r++) { al[r] = 0.f; ar[r] = 0.f; }

    #pragma unroll 4
    for (int k4 = 0; k4 < K / 4; k4++) {
        float wl0 = __ldg(&Wl[(k4 * 4 + 0) * 32 + col]);
        float wl1 = __ldg(&Wl[(k4 * 4 + 1) * 32 + col]);
        float wl2 = __ldg(&Wl[(k4 * 4 + 2) * 32 + col]);
        float wl3 = __ldg(&Wl[(k4 * 4 + 3) * 32 + col]);
        float wr0 = __ldg(&Wr[(k4 * 4 + 0) * 32 + col]);
        float wr1 = __ldg(&Wr[(k4 * 4 + 1) * 32 + col]);
        float wr2 = __ldg(&Wr[(k4 * 4 + 2) * 32 + col]);
        float wr3 = __ldg(&Wr[(k4 * 4 + 3) * 32 + col]);
        #pragma unroll
        for (int r = 0; r < 8; r++) {
            float4 xv = sx[(ty * 8 + r) * (K / 4) + k4];   // warp-uniform bcast
            al[r] = fmaf(xv.x, wl0, al[r]);
            al[r] = fmaf(xv.y, wl1, al[r]);
            al[r] = fmaf(xv.z, wl2, al[r]);
            al[r] = fmaf(xv.w, wl3, al[r]);
            ar[r] = fmaf(xv.x, wr0, ar[r]);
            ar[r] = fmaf(xv.y, wr1, ar[r]);
            ar[r] = fmaf(xv.z, wr2, ar[r]);
            ar[r] = fmaf(xv.w, wr3, ar[r]);
        }
    }
    float bL = bl[col], bR = br[col];
    int row0 = base + ty * 8;
    #pragma unroll
    for (int r = 0; r < 8; r++) {
        int row = row0 + r;
        if (row < N_NODES) {
            g_xl[row * 32 + col] = al[r] + bL;
            g_xr[row * 32 + col] = ar[r] + bR;
        }
    }
}

// Fused edge pass: 8 lanes per edge, each lane owns a float4 feature group.
// score -> p = exp(score) (shift-invariant softmax, no max pass) ->
// acc[d] += p * xl[s]  (red.v4),  z[d] += p.   zsel picks g_z1 / g_z2.
__global__ void k_edge(const int* __restrict__ src, const int* __restrict__ dst,
                       const float* __restrict__ ea,
                       const float* __restrict__ We, const float* __restrict__ att,
                       int zsel) {
    int g   = blockIdx.x * blockDim.x + threadIdx.x;
    int e   = g >> 3;
    int sub = g & 7;
    if (e >= ETOT) return;

    int s, d; float a;
    if (e < N_EDGES) { s = src[e]; d = dst[e]; a = ea[e]; }
    else             { s = e - N_EDGES; d = s; a = g_mean[s]; }

    // issue long-latency gathers first
    float4 xl4 = __ldg(&((const float4*)g_xl)[s * 8 + sub]);
    float4 xr4 = __ldg(&((const float4*)g_xr)[d * 8 + sub]);
    float4 W4  = __ldg(&((const float4*)We)[sub]);
    float4 A4  = __ldg(&((const float4*)att)[sub]);

    float v0 = xl4.x + xr4.x + a * W4.x;
    float v1 = xl4.y + xr4.y + a * W4.y;
    float v2 = xl4.z + xr4.z + a * W4.z;
    float v3 = xl4.w + xr4.w + a * W4.w;
    v0 = v0 > 0.f ? v0 : NEG_SLOPE * v0;
    v1 = v1 > 0.f ? v1 : NEG_SLOPE * v1;
    v2 = v2 > 0.f ? v2 : NEG_SLOPE * v2;
    v3 = v3 > 0.f ? v3 : NEG_SLOPE * v3;

    float t = v0 * A4.x + v1 * A4.y + v2 * A4.z + v3 * A4.w;
    t += __shfl_xor_sync(0xffffffffu, t, 1);
    t += __shfl_xor_sync(0xffffffffu, t, 2);
    t += __shfl_xor_sync(0xffffffffu, t, 4);

    float p = __expf(t);

    float c0 = p * xl4.x, c1 = p * xl4.y, c2 = p * xl4.z, c3 = p * xl4.w;
    float* dstp = &g_acc[d * 32 + sub * 4];
    asm volatile("red.global.add.v4.f32 [%0], {%1, %2, %3, %4};"
                 :: "l"(dstp), "f"(c0), "f"(c1), "f"(c2), "f"(c3) : "memory");
    if (sub == 0) atomicAdd(zsel ? &g_z2[d] : &g_z1[d], p);
}

// finalize: divide by z, add bias; layer1 -> relu into g_h, layer2 -> d_out.
// Resets only g_acc (read & written by the same thread -> race-free).
__global__ void k_fin(const float* __restrict__ b, float* __restrict__ out,
                      int zsel, int do_relu) {
    int i = blockIdx.x * blockDim.x + threadIdx.x;
    if (i >= N_NODES * FDIM) return;
    const float* z = zsel ? g_z2 : g_z1;
    float v = g_acc[i] / z[i >> 5] + b[i & 31];
    if (do_relu) g_h[i] = fmaxf(v, 0.0f);
    else         out[i] = v;
    g_acc[i] = 0.0f;                      // fused reset for next layer (safe)
}

// ---------------- launch ----------------------------------------------------
extern "C" void kernel_launch(void* const* d_in, const int* in_sizes, int n_in,
                              void* d_out, int out_size) {
    const float* x    = (const float*)d_in[0];
    const int*   src  = (const int*)  d_in[1];
    const int*   dst  = (const int*)  d_in[2];
    const float* ea   = (const float*)d_in[3];
    const float* Wl1  = (const float*)d_in[4];
    const float* bl1  = (const float*)d_in[5];
    const float* Wr1  = (const float*)d_in[6];
    const float* br1  = (const float*)d_in[7];
    const float* We1  = (const float*)d_in[8];
    const float* att1 = (const float*)d_in[9];
    const float* b1   = (const float*)d_in[10];
    const float* Wl2  = (const float*)d_in[11];
    const float* bl2  = (const float*)d_in[12];
    const float* Wr2  = (const float*)d_in[13];
    const float* br2  = (const float*)d_in[14];
    const float* We2  = (const float*)d_in[15];
    const float* att2 = (const float*)d_in[16];
    const float* b2   = (const float*)d_in[17];
    float* out = (float*)d_out;

    const int TB   = 256;
    const int NB32 = (N_NODES * FDIM + TB - 1) / TB;
    const int NB   = (N_NODES + TB - 1) / TB;
    const int EB   = (N_EDGES + TB - 1) / TB;
    const int XB   = ((long)ETOT * 8 + TB - 1) / TB;   // oct per edge
    const int GB   = (N_NODES + 63) / 64;

    // self-loop mean attrs (layer-invariant) + per-launch state reset
    k_init<<<NB32, TB>>>();
    k_stats<<<EB, TB>>>(dst, ea);
    k_mean<<<NB, TB>>>();

    // ---- layer 1 ----
    k_gemm<128><<<GB, TB>>>((const float4*)x, Wl1, bl1, Wr1, br1);
    k_edge<<<XB, TB>>>(src, dst, ea, We1, att1, 0);
    k_fin<<<NB32, TB>>>(b1, out, 0, 1);

    // ---- layer 2 ----
    k_gemm<32><<<GB, TB>>>(nullptr, Wl2, bl2, Wr2, br2);
    k_edge<<<XB, TB>>>(src, dst, ea, We2, att2, 1);
    k_fin<<<NB32, TB>>>(b2, out, 1, 0);
}